// round 2
// baseline (speedup 1.0000x reference)
#include <cuda_runtime.h>

// ---------------------------------------------------------------------------
// SINDy autoencoder forward (batch-1, pure HBM-bound, ~545MB weights/call):
//   z = enc(x); dz = J_enc(x) @ dx (forward-mode JVP, fused dual matvec)
//   theta = sindy_library(z); dzb = E_w @ theta + E_b
//   xb = dec(z); dxb = J_dec(z) @ dzb
// Output: [z(16) | dz(16) | dzb(16) | xb(16384) | dxb(16384)] = 32816 f32
// ---------------------------------------------------------------------------

#define W0_OUT 4096
#define W0_IN  16384
#define W1_OUT 1024
#define W1_IN  4096
#define LATENT 16
#define SINDY_DIM 984

// Scratch (device globals)
__device__ float g_pre1[W0_OUT], g_u1[W0_OUT];           // enc L0 raw
__device__ float g_pre2p[2 * W1_OUT], g_u2p[2 * W1_OUT]; // enc L1 split-K partials
__device__ float g_g1[1024],  g_p1[1024];                // dec L0 activated
__device__ float g_q2[4096],  g_v2[4096];                // dec L1 raw

__device__ __forceinline__ float sigf(float x) { return 1.0f / (1.0f + __expf(-x)); }

__device__ __forceinline__ float4 ldcs4(const float* p) {
    return __ldcs((const float4*)p);
}

// ---------------------------------------------------------------------------
// Dual matvec over a K-chunk: outA[row]=W@a(+bias), outB[row]=W@b.
// W points at (row0, chunk start); KSTRIDE = full row stride.
// SIG: on-the-fly a:=sigmoid(a_raw), b:=a(1-a)*b_raw.
// ---------------------------------------------------------------------------
template<int KSTRIDE, int KCHUNK, int ROWS, int THREADS, bool SIG>
__device__ __forceinline__ void dual_body(
    const float* __restrict__ W,
    const float* __restrict__ av,
    const float* __restrict__ bv,
    const float* __restrict__ bias,   // may be nullptr
    float* __restrict__ outA,
    float* __restrict__ outB,
    int row0)
{
    constexpr int NW = THREADS / 32;
    constexpr int ITERS = KCHUNK / (THREADS * 4);
    const int tid = threadIdx.x;

    float accA[ROWS], accB[ROWS];
#pragma unroll
    for (int r = 0; r < ROWS; r++) { accA[r] = 0.0f; accB[r] = 0.0f; }

#pragma unroll 4
    for (int it = 0; it < ITERS; it++) {
        const int k = (it * THREADS + tid) * 4;
        float4 a4 = *(const float4*)(av + k);
        float4 b4 = *(const float4*)(bv + k);
        if (SIG) {
            float s;
            s = sigf(a4.x); b4.x *= s * (1.0f - s); a4.x = s;
            s = sigf(a4.y); b4.y *= s * (1.0f - s); a4.y = s;
            s = sigf(a4.z); b4.z *= s * (1.0f - s); a4.z = s;
            s = sigf(a4.w); b4.w *= s * (1.0f - s); a4.w = s;
        }
#pragma unroll
        for (int r = 0; r < ROWS; r++) {
            const float4 w4 = ldcs4(W + (size_t)r * KSTRIDE + k);
            accA[r] = fmaf(w4.x, a4.x, accA[r]);
            accA[r] = fmaf(w4.y, a4.y, accA[r]);
            accA[r] = fmaf(w4.z, a4.z, accA[r]);
            accA[r] = fmaf(w4.w, a4.w, accA[r]);
            accB[r] = fmaf(w4.x, b4.x, accB[r]);
            accB[r] = fmaf(w4.y, b4.y, accB[r]);
            accB[r] = fmaf(w4.z, b4.z, accB[r]);
            accB[r] = fmaf(w4.w, b4.w, accB[r]);
        }
    }

    __shared__ float sA[NW][ROWS], sB[NW][ROWS];
    const int lane = tid & 31, warp = tid >> 5;
#pragma unroll
    for (int r = 0; r < ROWS; r++) {
        float vA = accA[r], vB = accB[r];
#pragma unroll
        for (int o = 16; o; o >>= 1) {
            vA += __shfl_xor_sync(0xffffffffu, vA, o);
            vB += __shfl_xor_sync(0xffffffffu, vB, o);
        }
        if (lane == 0) { sA[warp][r] = vA; sB[warp][r] = vB; }
    }
    __syncthreads();
    if (tid < ROWS) {
        float vA = 0.0f, vB = 0.0f;
#pragma unroll
        for (int w = 0; w < NW; w++) { vA += sA[w][tid]; vB += sB[w][tid]; }
        if (bias) vA += bias[row0 + tid];
        outA[row0 + tid] = vA;
        outB[row0 + tid] = vB;
    }
}

// enc L0: pre1 = W0 @ x + b0 ; u1 = W0 @ dx     (256 MB, 512 blocks, 1 wave)
__global__ void __launch_bounds__(256) k_enc0(
    const float* __restrict__ W, const float* __restrict__ x,
    const float* __restrict__ dx, const float* __restrict__ b)
{
    const int row0 = blockIdx.x * 8;
    dual_body<W0_IN, W0_IN, 8, 256, false>(
        W + (size_t)row0 * W0_IN, x, dx, b, g_pre1, g_u1, row0);
}

// enc L1, split-K x2: partials into g_pre2p/g_u2p (bias folded into split 0)
__global__ void __launch_bounds__(256) k_enc1(
    const float* __restrict__ W, const float* __restrict__ b)
{
    const int row0  = blockIdx.x * 8;
    const int split = blockIdx.y;                 // 0..1, chunk = 2048
    const int koff  = split * 2048;
    dual_body<W0_OUT, 2048, 8, 256, true>(
        W + (size_t)row0 * W0_OUT + koff,
        g_pre1 + koff, g_u1 + koff,
        split == 0 ? b : nullptr,
        g_pre2p + split * W1_OUT, g_u2p + split * W1_OUT, row0);
}

// dec L1: q2 = Wd1 @ g1 + bd1 ; v2 = Wd1 @ p1   (16 MB, 512 blocks)
__global__ void __launch_bounds__(256) k_dec1(
    const float* __restrict__ W, const float* __restrict__ b)
{
    const int row0 = blockIdx.x * 8;
    dual_body<1024, 1024, 8, 256, false>(
        W + (size_t)row0 * 1024, g_g1, g_p1, b, g_q2, g_v2, row0);
}

// dec L2 (sigmoid fused): xb, dxb straight into output  (256 MB, 2048 blocks)
__global__ void __launch_bounds__(256) k_dec2(
    const float* __restrict__ W, const float* __restrict__ b,
    float* __restrict__ out)
{
    const int row0 = blockIdx.x * 8;
    dual_body<4096, 4096, 8, 256, true>(
        W + (size_t)row0 * 4096, g_q2, g_v2, b, out + 48, out + 48 + 16384, row0);
}

// ---------------------------------------------------------------------------
// Middle chain, one block, 512 threads, everything prefetched into smem:
//   reduce enc-L1 partials -> h2,t2 -> z,dz -> theta -> dzb -> dec L0 (g1,p1)
// Dynamic smem layout (floats):
//   [0,16384)            we_w2
//   [16384,32128)        E_w (15744)
//   [32128,48512)        wd_w0 (16384)
//   [48512,49536)        h2
//   [49536,50560)        t2
//   [50560,51544)        theta
// ---------------------------------------------------------------------------
#define SM_WE2   0
#define SM_EW    16384
#define SM_WD0   32128
#define SM_H2    48512
#define SM_T2    49536
#define SM_THETA 50560
#define SM_FLOATS 51544
#define SM_BYTES (SM_FLOATS * 4)

__global__ void __launch_bounds__(512) k_small(
    const float* __restrict__ we_w2, const float* __restrict__ we_b2,
    const float* __restrict__ E_w,   const float* __restrict__ E_b,
    const float* __restrict__ wd_w0, const float* __restrict__ wd_b0,
    float* __restrict__ out)
{
    extern __shared__ float sm[];
    __shared__ float z[LATENT], dz[LATENT], dzb[LATENT];

    const int tid = threadIdx.x;
    const int lane = tid & 31, wid = tid >> 5;   // 16 warps

    // ---- prefetch phase: all global loads issued up front ----
    // we_w2: 16384 f = 4096 float4
    for (int i = tid; i < 4096; i += 512)
        *(float4*)(sm + SM_WE2 + i * 4) = ldcs4(we_w2 + i * 4);
    // E_w: 15744 f = 3936 float4
    for (int i = tid; i < 3936; i += 512)
        *(float4*)(sm + SM_EW + i * 4) = ldcs4(E_w + i * 4);
    // wd_w0: 16384 f = 4096 float4
    for (int i = tid; i < 4096; i += 512)
        *(float4*)(sm + SM_WD0 + i * 4) = ldcs4(wd_w0 + i * 4);
    // enc-L1 partial reduce + activation: h2, t2
    for (int i = tid; i < W1_OUT; i += 512) {
        float pre = g_pre2p[i] + g_pre2p[W1_OUT + i];     // bias already in split 0
        float u   = g_u2p[i]   + g_u2p[W1_OUT + i];
        float s = sigf(pre);
        sm[SM_H2 + i] = s;
        sm[SM_T2 + i] = s * (1.0f - s) * u;
    }
    __syncthreads();

    // ---- z = we_w2 @ h2 + b2 ; dz = we_w2 @ t2  (warp per row) ----
    {
        float az = 0.0f, ad = 0.0f;
        const float* wr = sm + SM_WE2 + wid * W1_OUT;
        for (int c = lane; c < W1_OUT; c += 32) {
            float w = wr[c];
            az = fmaf(w, sm[SM_H2 + c], az);
            ad = fmaf(w, sm[SM_T2 + c], ad);
        }
#pragma unroll
        for (int o = 16; o; o >>= 1) {
            az += __shfl_xor_sync(0xffffffffu, az, o);
            ad += __shfl_xor_sync(0xffffffffu, ad, o);
        }
        if (lane == 0) { z[wid] = az + we_b2[wid]; dz[wid] = ad; }
    }
    __syncthreads();

    if (tid < LATENT) { out[tid] = z[tid]; out[LATENT + tid] = dz[tid]; }

    // ---- theta ----
    for (int idx = tid; idx < SINDY_DIM; idx += 512) {
        float v;
        if (idx < 16) v = 1.0f;
        else if (idx < 32) v = z[idx - 16];
        else if (idx < 168) {
            int q = idx - 32, i = 0;
            for (;;) { int m = 16 - i; if (q < m) break; q -= m; i++; }
            v = z[i] * z[i + q];
        } else {
            int t = idx - 168, i = 0;
            for (;;) { int m = 16 - i; int c = m * (m + 1) / 2; if (t < c) break; t -= c; i++; }
            int j = i;
            for (;;) { int m = 16 - j; if (t < m) break; t -= m; j++; }
            v = z[i] * z[j] * z[j + t];
        }
        sm[SM_THETA + idx] = v;
    }
    __syncthreads();

    // ---- dzb = E_w @ theta + E_b  (warp per row) ----
    {
        float a = 0.0f;
        const float* er = sm + SM_EW + wid * SINDY_DIM;
        for (int c = lane; c < SINDY_DIM; c += 32)
            a = fmaf(er[c], sm[SM_THETA + c], a);
#pragma unroll
        for (int o = 16; o; o >>= 1)
            a += __shfl_xor_sync(0xffffffffu, a, o);
        if (lane == 0) dzb[wid] = a + E_b[wid];
    }
    __syncthreads();

    if (tid < LATENT) out[32 + tid] = dzb[tid];

    // ---- dec L0 + activation ----
    for (int row = tid; row < 1024; row += 512) {
        float a = wd_b0[row], bb = 0.0f;
        const float* wr = sm + SM_WD0 + row * LATENT;
#pragma unroll
        for (int c = 0; c < LATENT; c++) {
            float w = wr[c];
            a  = fmaf(w, z[c],   a);
            bb = fmaf(w, dzb[c], bb);
        }
        float s = sigf(a);
        g_g1[row] = s;
        g_p1[row] = s * (1.0f - s) * bb;
    }
}

extern "C" void kernel_launch(void* const* d_in, const int* in_sizes, int n_in,
                              void* d_out, int out_size)
{
    const float* x     = (const float*)d_in[0];
    const float* dx    = (const float*)d_in[1];
    const float* we_w0 = (const float*)d_in[3];
    const float* we_b0 = (const float*)d_in[4];
    const float* we_w1 = (const float*)d_in[5];
    const float* we_b1 = (const float*)d_in[6];
    const float* we_w2 = (const float*)d_in[7];
    const float* we_b2 = (const float*)d_in[8];
    const float* wd_w0 = (const float*)d_in[9];
    const float* wd_b0 = (const float*)d_in[10];
    const float* wd_w1 = (const float*)d_in[11];
    const float* wd_b1 = (const float*)d_in[12];
    const float* wd_w2 = (const float*)d_in[13];
    const float* wd_b2 = (const float*)d_in[14];
    const float* E_w   = (const float*)d_in[15];
    const float* E_b   = (const float*)d_in[16];
    float* out = (float*)d_out;

    cudaFuncSetAttribute(k_small, cudaFuncAttributeMaxDynamicSharedMemorySize, SM_BYTES);

    k_enc0<<<W0_OUT / 8, 256>>>(we_w0, x, dx, we_b0);          // 256 MB
    {
        dim3 g(W1_OUT / 8, 2);                                  // split-K x2
        k_enc1<<<g, 256>>>(we_w1, we_b1);                       // 16 MB
    }
    k_small<<<1, 512, SM_BYTES>>>(we_w2, we_b2, E_w, E_b, wd_w0, wd_b0, out);
    k_dec1<<<4096 / 8, 256>>>(wd_w1, wd_b1);                    // 16 MB
    k_dec2<<<16384 / 8, 256>>>(wd_w2, wd_b2, out);              // 256 MB
}

// round 3
// speedup vs baseline: 1.0730x; 1.0730x over previous
#include <cuda_runtime.h>

// ---------------------------------------------------------------------------
// SINDy autoencoder forward (batch-1, HBM-bound, ~545MB weights/call).
// Output: [z(16) | dz(16) | dzb(16) | xb(16384) | dxb(16384)] = 32816 f32
// R3: ROWS=4 per block (was 8) -> lower reg pressure, batched weight loads,
//     ~2x occupancy, higher memory-level parallelism.
// ---------------------------------------------------------------------------

#define W0_OUT 4096
#define W0_IN  16384
#define W1_OUT 1024
#define LATENT 16
#define SINDY_DIM 984

__device__ float g_pre1[W0_OUT], g_u1[W0_OUT];
__device__ float g_pre2p[2 * W1_OUT], g_u2p[2 * W1_OUT];
__device__ float g_g1[1024],  g_p1[1024];
__device__ float g_q2[4096],  g_v2[4096];

__device__ __forceinline__ float sigf(float x) { return 1.0f / (1.0f + __expf(-x)); }
__device__ __forceinline__ float4 ldcs4(const float* p) { return __ldcs((const float4*)p); }

// ---------------------------------------------------------------------------
// Dual matvec over a K-chunk: outA[row]=W@a(+bias), outB[row]=W@b.
// ---------------------------------------------------------------------------
template<int KSTRIDE, int KCHUNK, int ROWS, int THREADS, bool SIG>
__device__ __forceinline__ void dual_body(
    const float* __restrict__ W,
    const float* __restrict__ av,
    const float* __restrict__ bv,
    const float* __restrict__ bias,
    float* __restrict__ outA,
    float* __restrict__ outB,
    int row0)
{
    constexpr int NW = THREADS / 32;
    constexpr int ITERS = KCHUNK / (THREADS * 4);
    const int tid = threadIdx.x;

    float accA[ROWS], accB[ROWS];
#pragma unroll
    for (int r = 0; r < ROWS; r++) { accA[r] = 0.0f; accB[r] = 0.0f; }

#pragma unroll 2
    for (int it = 0; it < ITERS; it++) {
        const int k = (it * THREADS + tid) * 4;
        // batch all loads up front: 4 weight rows + 2 activation vectors
        float4 w4[ROWS];
#pragma unroll
        for (int r = 0; r < ROWS; r++)
            w4[r] = ldcs4(W + (size_t)r * KSTRIDE + k);
        float4 a4 = *(const float4*)(av + k);
        float4 b4 = *(const float4*)(bv + k);
        if (SIG) {
            float s;
            s = sigf(a4.x); b4.x *= s * (1.0f - s); a4.x = s;
            s = sigf(a4.y); b4.y *= s * (1.0f - s); a4.y = s;
            s = sigf(a4.z); b4.z *= s * (1.0f - s); a4.z = s;
            s = sigf(a4.w); b4.w *= s * (1.0f - s); a4.w = s;
        }
#pragma unroll
        for (int r = 0; r < ROWS; r++) {
            accA[r] = fmaf(w4[r].x, a4.x, accA[r]);
            accA[r] = fmaf(w4[r].y, a4.y, accA[r]);
            accA[r] = fmaf(w4[r].z, a4.z, accA[r]);
            accA[r] = fmaf(w4[r].w, a4.w, accA[r]);
            accB[r] = fmaf(w4[r].x, b4.x, accB[r]);
            accB[r] = fmaf(w4[r].y, b4.y, accB[r]);
            accB[r] = fmaf(w4[r].z, b4.z, accB[r]);
            accB[r] = fmaf(w4[r].w, b4.w, accB[r]);
        }
    }

    __shared__ float sA[NW][ROWS], sB[NW][ROWS];
    const int lane = tid & 31, warp = tid >> 5;
#pragma unroll
    for (int r = 0; r < ROWS; r++) {
        float vA = accA[r], vB = accB[r];
#pragma unroll
        for (int o = 16; o; o >>= 1) {
            vA += __shfl_xor_sync(0xffffffffu, vA, o);
            vB += __shfl_xor_sync(0xffffffffu, vB, o);
        }
        if (lane == 0) { sA[warp][r] = vA; sB[warp][r] = vB; }
    }
    __syncthreads();
    if (tid < ROWS) {
        float vA = 0.0f, vB = 0.0f;
#pragma unroll
        for (int w = 0; w < NW; w++) { vA += sA[w][tid]; vB += sB[w][tid]; }
        if (bias) vA += bias[row0 + tid];
        outA[row0 + tid] = vA;
        outB[row0 + tid] = vB;
    }
}

// enc L0: pre1 = W0 @ x + b0 ; u1 = W0 @ dx  (256 MB, 1024 blocks)
__global__ void __launch_bounds__(256) k_enc0(
    const float* __restrict__ W, const float* __restrict__ x,
    const float* __restrict__ dx, const float* __restrict__ b)
{
    const int row0 = blockIdx.x * 4;
    dual_body<W0_IN, W0_IN, 4, 256, false>(
        W + (size_t)row0 * W0_IN, x, dx, b, g_pre1, g_u1, row0);
}

// enc L1, split-K x2 (16 MB, 512 blocks)
__global__ void __launch_bounds__(256) k_enc1(
    const float* __restrict__ W, const float* __restrict__ b)
{
    const int row0  = blockIdx.x * 4;
    const int split = blockIdx.y;
    const int koff  = split * 2048;
    dual_body<W0_OUT, 2048, 4, 256, true>(
        W + (size_t)row0 * W0_OUT + koff,
        g_pre1 + koff, g_u1 + koff,
        split == 0 ? b : nullptr,
        g_pre2p + split * W1_OUT, g_u2p + split * W1_OUT, row0);
}

// dec L1 (16 MB, 1024 blocks)
__global__ void __launch_bounds__(256) k_dec1(
    const float* __restrict__ W, const float* __restrict__ b)
{
    const int row0 = blockIdx.x * 4;
    dual_body<1024, 1024, 4, 256, false>(
        W + (size_t)row0 * 1024, g_g1, g_p1, b, g_q2, g_v2, row0);
}

// dec L2 (256 MB, 4096 blocks)
__global__ void __launch_bounds__(256) k_dec2(
    const float* __restrict__ W, const float* __restrict__ b,
    float* __restrict__ out)
{
    const int row0 = blockIdx.x * 4;
    dual_body<4096, 4096, 4, 256, true>(
        W + (size_t)row0 * 4096, g_q2, g_v2, b, out + 48, out + 48 + 16384, row0);
}

// ---------------------------------------------------------------------------
// Middle chain, one block, 512 threads, weights prefetched to smem.
// ---------------------------------------------------------------------------
#define SM_WE2   0
#define SM_EW    16384
#define SM_WD0   32128
#define SM_H2    48512
#define SM_T2    49536
#define SM_THETA 50560
#define SM_FLOATS 51544
#define SM_BYTES (SM_FLOATS * 4)

__global__ void __launch_bounds__(512) k_small(
    const float* __restrict__ we_w2, const float* __restrict__ we_b2,
    const float* __restrict__ E_w,   const float* __restrict__ E_b,
    const float* __restrict__ wd_w0, const float* __restrict__ wd_b0,
    float* __restrict__ out)
{
    extern __shared__ float sm[];
    __shared__ float z[LATENT], dz[LATENT], dzb[LATENT];

    const int tid = threadIdx.x;
    const int lane = tid & 31, wid = tid >> 5;

    for (int i = tid; i < 4096; i += 512)
        *(float4*)(sm + SM_WE2 + i * 4) = ldcs4(we_w2 + i * 4);
    for (int i = tid; i < 3936; i += 512)
        *(float4*)(sm + SM_EW + i * 4) = ldcs4(E_w + i * 4);
    for (int i = tid; i < 4096; i += 512)
        *(float4*)(sm + SM_WD0 + i * 4) = ldcs4(wd_w0 + i * 4);
    for (int i = tid; i < W1_OUT; i += 512) {
        float pre = g_pre2p[i] + g_pre2p[W1_OUT + i];
        float u   = g_u2p[i]   + g_u2p[W1_OUT + i];
        float s = sigf(pre);
        sm[SM_H2 + i] = s;
        sm[SM_T2 + i] = s * (1.0f - s) * u;
    }
    __syncthreads();

    {
        float az = 0.0f, ad = 0.0f;
        const float* wr = sm + SM_WE2 + wid * W1_OUT;
        for (int c = lane; c < W1_OUT; c += 32) {
            float w = wr[c];
            az = fmaf(w, sm[SM_H2 + c], az);
            ad = fmaf(w, sm[SM_T2 + c], ad);
        }
#pragma unroll
        for (int o = 16; o; o >>= 1) {
            az += __shfl_xor_sync(0xffffffffu, az, o);
            ad += __shfl_xor_sync(0xffffffffu, ad, o);
        }
        if (lane == 0) { z[wid] = az + we_b2[wid]; dz[wid] = ad; }
    }
    __syncthreads();

    if (tid < LATENT) { out[tid] = z[tid]; out[LATENT + tid] = dz[tid]; }

    for (int idx = tid; idx < SINDY_DIM; idx += 512) {
        float v;
        if (idx < 16) v = 1.0f;
        else if (idx < 32) v = z[idx - 16];
        else if (idx < 168) {
            int q = idx - 32, i = 0;
            for (;;) { int m = 16 - i; if (q < m) break; q -= m; i++; }
            v = z[i] * z[i + q];
        } else {
            int t = idx - 168, i = 0;
            for (;;) { int m = 16 - i; int c = m * (m + 1) / 2; if (t < c) break; t -= c; i++; }
            int j = i;
            for (;;) { int m = 16 - j; if (t < m) break; t -= m; j++; }
            v = z[i] * z[j] * z[j + t];
        }
        sm[SM_THETA + idx] = v;
    }
    __syncthreads();

    {
        float a = 0.0f;
        const float* er = sm + SM_EW + wid * SINDY_DIM;
        for (int c = lane; c < SINDY_DIM; c += 32)
            a = fmaf(er[c], sm[SM_THETA + c], a);
#pragma unroll
        for (int o = 16; o; o >>= 1)
            a += __shfl_xor_sync(0xffffffffu, a, o);
        if (lane == 0) dzb[wid] = a + E_b[wid];
    }
    __syncthreads();

    if (tid < LATENT) out[32 + tid] = dzb[tid];

    for (int row = tid; row < 1024; row += 512) {
        float a = wd_b0[row], bb = 0.0f;
        const float* wr = sm + SM_WD0 + row * LATENT;
#pragma unroll
        for (int c = 0; c < LATENT; c++) {
            float w = wr[c];
            a  = fmaf(w, z[c],   a);
            bb = fmaf(w, dzb[c], bb);
        }
        float s = sigf(a);
        g_g1[row] = s;
        g_p1[row] = s * (1.0f - s) * bb;
    }
}

extern "C" void kernel_launch(void* const* d_in, const int* in_sizes, int n_in,
                              void* d_out, int out_size)
{
    const float* x     = (const float*)d_in[0];
    const float* dx    = (const float*)d_in[1];
    const float* we_w0 = (const float*)d_in[3];
    const float* we_b0 = (const float*)d_in[4];
    const float* we_w1 = (const float*)d_in[5];
    const float* we_b1 = (const float*)d_in[6];
    const float* we_w2 = (const float*)d_in[7];
    const float* we_b2 = (const float*)d_in[8];
    const float* wd_w0 = (const float*)d_in[9];
    const float* wd_b0 = (const float*)d_in[10];
    const float* wd_w1 = (const float*)d_in[11];
    const float* wd_b1 = (const float*)d_in[12];
    const float* wd_w2 = (const float*)d_in[13];
    const float* wd_b2 = (const float*)d_in[14];
    const float* E_w   = (const float*)d_in[15];
    const float* E_b   = (const float*)d_in[16];
    float* out = (float*)d_out;

    cudaFuncSetAttribute(k_small, cudaFuncAttributeMaxDynamicSharedMemorySize, SM_BYTES);

    k_enc0<<<W0_OUT / 4, 256>>>(we_w0, x, dx, we_b0);          // 256 MB
    {
        dim3 g(W1_OUT / 4, 2);
        k_enc1<<<g, 256>>>(we_w1, we_b1);                       // 16 MB
    }
    k_small<<<1, 512, SM_BYTES>>>(we_w2, we_b2, E_w, E_b, wd_w0, wd_b0, out);
    k_dec1<<<4096 / 4, 256>>>(wd_w1, wd_b1);                    // 16 MB
    k_dec2<<<16384 / 4, 256>>>(wd_w2, wd_b2, out);              // 256 MB
}

// round 4
// speedup vs baseline: 1.1365x; 1.0591x over previous
#include <cuda_runtime.h>

// ---------------------------------------------------------------------------
// SINDy autoencoder forward (batch-1, HBM-bound, ~545MB weights/call).
// Output: [z(16) | dz(16) | dzb(16) | xb(16384) | dxb(16384)] = 32816 f32
// R4: PDL (programmatic dependent launch) — each kernel triggers its
//     dependent immediately, dependents prefetch their weight tiles to L2
//     before griddepcontrol.wait, overlapping DRAM streams across the chain.
// ---------------------------------------------------------------------------

#define W0_OUT 4096
#define W0_IN  16384
#define W1_OUT 1024
#define LATENT 16
#define SINDY_DIM 984

__device__ float g_pre1[W0_OUT], g_u1[W0_OUT];
__device__ float g_pre2p[2 * W1_OUT], g_u2p[2 * W1_OUT];
__device__ float g_g1[1024],  g_p1[1024];
__device__ float g_q2[4096],  g_v2[4096];

__device__ __forceinline__ float sigf(float x) { return 1.0f / (1.0f + __expf(-x)); }
__device__ __forceinline__ float4 ldcs4(const float* p) { return __ldcs((const float4*)p); }

__device__ __forceinline__ void pdl_trigger() {
    asm volatile("griddepcontrol.launch_dependents;" ::: "memory");
}
__device__ __forceinline__ void pdl_wait() {
    asm volatile("griddepcontrol.wait;" ::: "memory");
}
__device__ __forceinline__ void l2_prefetch(const void* p) {
    asm volatile("prefetch.global.L2 [%0];" :: "l"(p));
}

// Prefetch [base, base+bytes) to L2, strided by whole block.
template<int THREADS>
__device__ __forceinline__ void prefetch_tile(const float* base, int bytes) {
    const char* p = (const char*)base;
    for (int off = threadIdx.x * 128; off < bytes; off += THREADS * 128)
        l2_prefetch(p + off);
}

// ---------------------------------------------------------------------------
// Dual matvec over a K-chunk: outA[row]=W@a(+bias), outB[row]=W@b.
// ---------------------------------------------------------------------------
template<int KSTRIDE, int KCHUNK, int ROWS, int THREADS, bool SIG>
__device__ __forceinline__ void dual_body(
    const float* __restrict__ W,
    const float* __restrict__ av,
    const float* __restrict__ bv,
    const float* __restrict__ bias,
    float* __restrict__ outA,
    float* __restrict__ outB,
    int row0)
{
    constexpr int NW = THREADS / 32;
    constexpr int ITERS = KCHUNK / (THREADS * 4);
    const int tid = threadIdx.x;

    float accA[ROWS], accB[ROWS];
#pragma unroll
    for (int r = 0; r < ROWS; r++) { accA[r] = 0.0f; accB[r] = 0.0f; }

#pragma unroll 2
    for (int it = 0; it < ITERS; it++) {
        const int k = (it * THREADS + tid) * 4;
        float4 w4[ROWS];
#pragma unroll
        for (int r = 0; r < ROWS; r++)
            w4[r] = ldcs4(W + (size_t)r * KSTRIDE + k);
        float4 a4 = *(const float4*)(av + k);
        float4 b4 = *(const float4*)(bv + k);
        if (SIG) {
            float s;
            s = sigf(a4.x); b4.x *= s * (1.0f - s); a4.x = s;
            s = sigf(a4.y); b4.y *= s * (1.0f - s); a4.y = s;
            s = sigf(a4.z); b4.z *= s * (1.0f - s); a4.z = s;
            s = sigf(a4.w); b4.w *= s * (1.0f - s); a4.w = s;
        }
#pragma unroll
        for (int r = 0; r < ROWS; r++) {
            accA[r] = fmaf(w4[r].x, a4.x, accA[r]);
            accA[r] = fmaf(w4[r].y, a4.y, accA[r]);
            accA[r] = fmaf(w4[r].z, a4.z, accA[r]);
            accA[r] = fmaf(w4[r].w, a4.w, accA[r]);
            accB[r] = fmaf(w4[r].x, b4.x, accB[r]);
            accB[r] = fmaf(w4[r].y, b4.y, accB[r]);
            accB[r] = fmaf(w4[r].z, b4.z, accB[r]);
            accB[r] = fmaf(w4[r].w, b4.w, accB[r]);
        }
    }

    __shared__ float sA[NW][ROWS], sB[NW][ROWS];
    const int lane = tid & 31, warp = tid >> 5;
#pragma unroll
    for (int r = 0; r < ROWS; r++) {
        float vA = accA[r], vB = accB[r];
#pragma unroll
        for (int o = 16; o; o >>= 1) {
            vA += __shfl_xor_sync(0xffffffffu, vA, o);
            vB += __shfl_xor_sync(0xffffffffu, vB, o);
        }
        if (lane == 0) { sA[warp][r] = vA; sB[warp][r] = vB; }
    }
    __syncthreads();
    if (tid < ROWS) {
        float vA = 0.0f, vB = 0.0f;
#pragma unroll
        for (int w = 0; w < NW; w++) { vA += sA[w][tid]; vB += sB[w][tid]; }
        if (bias) vA += bias[row0 + tid];
        outA[row0 + tid] = vA;
        outB[row0 + tid] = vB;
    }
}

// enc L0 (first in chain; no wait needed)
__global__ void __launch_bounds__(256) k_enc0(
    const float* __restrict__ W, const float* __restrict__ x,
    const float* __restrict__ dx, const float* __restrict__ b)
{
    pdl_trigger();
    const int row0 = blockIdx.x * 4;
    pdl_wait();   // no-op vs stream order; keeps pattern uniform
    dual_body<W0_IN, W0_IN, 4, 256, false>(
        W + (size_t)row0 * W0_IN, x, dx, b, g_pre1, g_u1, row0);
}

// enc L1, split-K x2
__global__ void __launch_bounds__(256) k_enc1(
    const float* __restrict__ W, const float* __restrict__ b)
{
    pdl_trigger();
    const int row0  = blockIdx.x * 4;
    const int split = blockIdx.y;
    const int koff  = split * 2048;
    const float* Wt = W + (size_t)row0 * W0_OUT + koff;
    // prefetch 4 rows x 2048 f = 4 x 8KB (rows not contiguous due to split)
#pragma unroll
    for (int r = 0; r < 4; r++)
        prefetch_tile<256>(Wt + (size_t)r * W0_OUT, 8192);
    pdl_wait();
    dual_body<W0_OUT, 2048, 4, 256, true>(
        Wt, g_pre1 + koff, g_u1 + koff,
        split == 0 ? b : nullptr,
        g_pre2p + split * W1_OUT, g_u2p + split * W1_OUT, row0);
}

// dec L1
__global__ void __launch_bounds__(256) k_dec1(
    const float* __restrict__ W, const float* __restrict__ b)
{
    pdl_trigger();
    const int row0 = blockIdx.x * 4;
    const float* Wt = W + (size_t)row0 * 1024;
    prefetch_tile<256>(Wt, 4 * 1024 * 4);   // 16 KB contiguous
    pdl_wait();
    dual_body<1024, 1024, 4, 256, false>(
        Wt, g_g1, g_p1, b, g_q2, g_v2, row0);
}

// dec L2 (last; writes final outputs)
__global__ void __launch_bounds__(256) k_dec2(
    const float* __restrict__ W, const float* __restrict__ b,
    float* __restrict__ out)
{
    const int row0 = blockIdx.x * 4;
    const float* Wt = W + (size_t)row0 * 4096;
    prefetch_tile<256>(Wt, 4 * 4096 * 4);   // 64 KB contiguous
    pdl_wait();
    dual_body<4096, 4096, 4, 256, true>(
        Wt, g_q2, g_v2, b, out + 48, out + 48 + 16384, row0);
}

// ---------------------------------------------------------------------------
// Middle chain, one block, 512 threads, weights prefetched to smem.
// ---------------------------------------------------------------------------
#define SM_WE2   0
#define SM_EW    16384
#define SM_WD0   32128
#define SM_H2    48512
#define SM_T2    49536
#define SM_THETA 50560
#define SM_FLOATS 51544
#define SM_BYTES (SM_FLOATS * 4)

__global__ void __launch_bounds__(512) k_small(
    const float* __restrict__ we_w2, const float* __restrict__ we_b2,
    const float* __restrict__ E_w,   const float* __restrict__ E_b,
    const float* __restrict__ wd_w0, const float* __restrict__ wd_b0,
    float* __restrict__ out)
{
    extern __shared__ float sm[];
    __shared__ float z[LATENT], dz[LATENT], dzb[LATENT];

    const int tid = threadIdx.x;
    const int lane = tid & 31, wid = tid >> 5;

    pdl_trigger();
    // prefetch all weights for this kernel into L2 before waiting
    prefetch_tile<512>(we_w2, 16384 * 4);
    prefetch_tile<512>(E_w,   15744 * 4);
    prefetch_tile<512>(wd_w0, 16384 * 4);
    pdl_wait();

    for (int i = tid; i < 4096; i += 512)
        *(float4*)(sm + SM_WE2 + i * 4) = ldcs4(we_w2 + i * 4);
    for (int i = tid; i < 3936; i += 512)
        *(float4*)(sm + SM_EW + i * 4) = ldcs4(E_w + i * 4);
    for (int i = tid; i < 4096; i += 512)
        *(float4*)(sm + SM_WD0 + i * 4) = ldcs4(wd_w0 + i * 4);
    for (int i = tid; i < W1_OUT; i += 512) {
        float pre = g_pre2p[i] + g_pre2p[W1_OUT + i];
        float u   = g_u2p[i]   + g_u2p[W1_OUT + i];
        float s = sigf(pre);
        sm[SM_H2 + i] = s;
        sm[SM_T2 + i] = s * (1.0f - s) * u;
    }
    __syncthreads();

    {
        float az = 0.0f, ad = 0.0f;
        const float* wr = sm + SM_WE2 + wid * W1_OUT;
        for (int c = lane; c < W1_OUT; c += 32) {
            float w = wr[c];
            az = fmaf(w, sm[SM_H2 + c], az);
            ad = fmaf(w, sm[SM_T2 + c], ad);
        }
#pragma unroll
        for (int o = 16; o; o >>= 1) {
            az += __shfl_xor_sync(0xffffffffu, az, o);
            ad += __shfl_xor_sync(0xffffffffu, ad, o);
        }
        if (lane == 0) { z[wid] = az + we_b2[wid]; dz[wid] = ad; }
    }
    __syncthreads();

    if (tid < LATENT) { out[tid] = z[tid]; out[LATENT + tid] = dz[tid]; }

    for (int idx = tid; idx < SINDY_DIM; idx += 512) {
        float v;
        if (idx < 16) v = 1.0f;
        else if (idx < 32) v = z[idx - 16];
        else if (idx < 168) {
            int q = idx - 32, i = 0;
            for (;;) { int m = 16 - i; if (q < m) break; q -= m; i++; }
            v = z[i] * z[i + q];
        } else {
            int t = idx - 168, i = 0;
            for (;;) { int m = 16 - i; int c = m * (m + 1) / 2; if (t < c) break; t -= c; i++; }
            int j = i;
            for (;;) { int m = 16 - j; if (t < m) break; t -= m; j++; }
            v = z[i] * z[j] * z[j + t];
        }
        sm[SM_THETA + idx] = v;
    }
    __syncthreads();

    {
        float a = 0.0f;
        const float* er = sm + SM_EW + wid * SINDY_DIM;
        for (int c = lane; c < SINDY_DIM; c += 32)
            a = fmaf(er[c], sm[SM_THETA + c], a);
#pragma unroll
        for (int o = 16; o; o >>= 1)
            a += __shfl_xor_sync(0xffffffffu, a, o);
        if (lane == 0) dzb[wid] = a + E_b[wid];
    }
    __syncthreads();

    if (tid < LATENT) out[32 + tid] = dzb[tid];

    for (int row = tid; row < 1024; row += 512) {
        float a = wd_b0[row], bb = 0.0f;
        const float* wr = sm + SM_WD0 + row * LATENT;
#pragma unroll
        for (int c = 0; c < LATENT; c++) {
            float w = wr[c];
            a  = fmaf(w, z[c],   a);
            bb = fmaf(w, dzb[c], bb);
        }
        float s = sigf(a);
        g_g1[row] = s;
        g_p1[row] = s * (1.0f - s) * bb;
    }
}

// ---------------------------------------------------------------------------
// Host: launch chain with programmatic stream serialization on every launch.
// ---------------------------------------------------------------------------
extern "C" void kernel_launch(void* const* d_in, const int* in_sizes, int n_in,
                              void* d_out, int out_size)
{
    const float* x     = (const float*)d_in[0];
    const float* dx    = (const float*)d_in[1];
    const float* we_w0 = (const float*)d_in[3];
    const float* we_b0 = (const float*)d_in[4];
    const float* we_w1 = (const float*)d_in[5];
    const float* we_b1 = (const float*)d_in[6];
    const float* we_w2 = (const float*)d_in[7];
    const float* we_b2 = (const float*)d_in[8];
    const float* wd_w0 = (const float*)d_in[9];
    const float* wd_b0 = (const float*)d_in[10];
    const float* wd_w1 = (const float*)d_in[11];
    const float* wd_b1 = (const float*)d_in[12];
    const float* wd_w2 = (const float*)d_in[13];
    const float* wd_b2 = (const float*)d_in[14];
    const float* E_w   = (const float*)d_in[15];
    const float* E_b   = (const float*)d_in[16];
    float* out = (float*)d_out;

    cudaFuncSetAttribute(k_small, cudaFuncAttributeMaxDynamicSharedMemorySize, SM_BYTES);

    cudaLaunchAttribute attr[1];
    attr[0].id = cudaLaunchAttributeProgrammaticStreamSerialization;
    attr[0].val.programmaticStreamSerializationAllowed = 1;

    cudaLaunchConfig_t cfg{};
    cfg.blockDim = dim3(256, 1, 1);
    cfg.dynamicSmemBytes = 0;
    cfg.stream = 0;
    cfg.attrs = attr;
    cfg.numAttrs = 1;

    // 1) enc L0 (256 MB)
    cfg.gridDim = dim3(W0_OUT / 4, 1, 1);
    cudaLaunchKernelEx(&cfg, k_enc0, we_w0, x, dx, we_b0);

    // 2) enc L1 (16 MB, split-K x2)
    cfg.gridDim = dim3(W1_OUT / 4, 2, 1);
    cudaLaunchKernelEx(&cfg, k_enc1, we_w1, we_b1);

    // 3) middle chain
    {
        cudaLaunchConfig_t cs = cfg;
        cs.gridDim = dim3(1, 1, 1);
        cs.blockDim = dim3(512, 1, 1);
        cs.dynamicSmemBytes = SM_BYTES;
        cudaLaunchKernelEx(&cs, k_small, we_w2, we_b2, E_w, E_b, wd_w0, wd_b0, out);
    }

    // 4) dec L1 (16 MB)
    cfg.gridDim = dim3(4096 / 4, 1, 1);
    cudaLaunchKernelEx(&cfg, k_dec1, wd_w1, wd_b1);

    // 5) dec L2 (256 MB)
    cfg.gridDim = dim3(16384 / 4, 1, 1);
    cudaLaunchKernelEx(&cfg, k_dec2, wd_w2, wd_b2, out);
}